// round 7
// baseline (speedup 1.0000x reference)
#include <cuda_runtime.h>
#include <math.h>

// Sinkhorn approximate EMD: B=8, N=2048, 3D points, 50 iterations.
// R7: single fused persistent kernel, cluster(8) = one batch, 64 CTAs.
// Exp-vectors live ONLY in shared memory: each group leader scatters its
// new exp value into all 8 cluster CTAs' smem (mapa + st.shared::cluster),
// double-buffered ping-pong, one cluster.sync per half-iteration. No global
// traffic in the main loop except the L1-resident packed-ELL gather stream.
// u kept in registers for the epilogue; cross-CTA sum also via DSMEM.

#define BB 8
#define NN 2048
#define NROWS (BB * NN)          // 16384
#define RSTRIDE 512              // padded max nnz per row (avg ~104, max ~340)
#define D2CUT 0.690776f          // -ln(1e-30)/100
#define CL 8                     // CTAs per cluster = per batch
#define RPC 256                  // rows per CTA (NN / CL)
#define TPB 1024                 // 256 groups x 4 lanes

__device__ unsigned g_pk[2][(size_t)NROWS * RSTRIDE];   // packed K / K^T (64 MB)

// pack: round-to-nearest on kept 21 high bits, low 11 bits = column index
__device__ __forceinline__ unsigned packf(float f, unsigned c) {
    return ((__float_as_uint(f) + 0x400u) & 0xFFFFF800u) | c;
}

__device__ __forceinline__ unsigned smem_u32(const void* p) {
    unsigned a;
    asm("{ .reg .u64 t; cvta.to.shared.u64 t, %1; cvt.u32.u64 %0, t; }"
        : "=r"(a) : "l"(p));
    return a;
}
__device__ __forceinline__ unsigned ctarank() {
    unsigned r; asm("mov.u32 %0, %%cluster_ctarank;" : "=r"(r)); return r;
}
__device__ __forceinline__ unsigned mapa_sm(unsigned addr, unsigned rank) {
    unsigned r;
    asm("mapa.shared::cluster.u32 %0, %1, %2;" : "=r"(r) : "r"(addr), "r"(rank));
    return r;
}
__device__ __forceinline__ void st_cluster(unsigned addr, float v) {
    asm volatile("st.shared::cluster.f32 [%0], %1;" :: "r"(addr), "f"(v) : "memory");
}
#define CLUSTER_SYNC() do {                                              \
    asm volatile("barrier.cluster.arrive.aligned;" ::: "memory");        \
    asm volatile("barrier.cluster.wait.aligned;"   ::: "memory");        \
} while (0)

// ---------------------------------------------------------------------------
__global__ __cluster_dims__(CL, 1, 1) __launch_bounds__(TPB, 1)
void fused_sinkhorn(const float* __restrict__ x1, const float* __restrict__ x2,
                    float* __restrict__ out, float logm) {
    __shared__ float pool[NN * 3];           // build staging; then 2 ping-pong bufs
    __shared__ unsigned char sit[2][RPC];    // per-row 16-entry iteration counts
    __shared__ float red[32];
    __shared__ float cred[CL];

    int batch = blockIdx.x >> 3;
    unsigned crank = ctarank();
    int t = threadIdx.x, warp = t >> 5, lane = t & 31;
    int rowbase = batch * NN + (int)crank * RPC;

    // ===== inline build: CTA-private packed-ELL rows of K and K^T =====
    #pragma unroll 1
    for (int m = 0; m < 2; ++m) {
        const float* rowpts = m ? x2 : x1;
        const float* colpts = m ? x1 : x2;
        const float* cp = colpts + (size_t)batch * NN * 3;
        for (int i = t; i < NN * 3; i += TPB) pool[i] = cp[i];
        __syncthreads();

        #pragma unroll 1
        for (int rr = 0; rr < RPC / 32; ++rr) {          // 8 rows per warp
            int r   = warp * (RPC / 32) + rr;
            int row = rowbase + r;
            const float* ap = rowpts + (size_t)row * 3;
            float ax = ap[0], ay = ap[1], az = ap[2];
            unsigned* krow = g_pk[m] + (size_t)row * RSTRIDE;

            unsigned base = 0;
            for (int c0 = 0; c0 < NN; c0 += 32) {
                int c = c0 + lane;
                float dx = ax - pool[3 * c];
                float dy = ay - pool[3 * c + 1];
                float dz = az - pool[3 * c + 2];
                float d2 = fmaf(dx, dx, fmaf(dy, dy, dz * dz));
                bool p = d2 < D2CUT;
                unsigned mk = __ballot_sync(0xffffffffu, p);
                if (p) {
                    unsigned idx = base + __popc(mk & ((1u << lane) - 1u));
                    if (idx < RSTRIDE)
                        krow[idx] = packf(__expf(-100.0f * d2), (unsigned)c);
                }
                base += __popc(mk);
            }
            unsigned nnz = (base < RSTRIDE) ? base : RSTRIDE;
            unsigned pad = (nnz + 15u) & ~15u;           // 16-entry group iters
            for (unsigned idx = nnz + lane; idx < pad; idx += 32) krow[idx] = 0u;
            if (lane == 0) sit[m][r] = (unsigned char)(pad >> 4);
        }
        __syncthreads();
    }

    // ping-pong exp-vector buffers inside pool
    float* buf0 = pool;
    float* buf1 = pool + NN;
    unsigned buf_base = smem_u32(pool);      // byte address of buf0

    // init buf0 = exp(v0) = 1
    if (t < NN / 4) ((float4*)buf0)[t] = make_float4(1.f, 1.f, 1.f, 1.f);

    int g  = t >> 2;                          // 256 groups; group g owns local row g
    int gl = t & 3;
    int myrow = rowbase + g;
    unsigned dst_off = (unsigned)((crank * RPC + g) * 4);   // byte off within a buf
    float myeu = 0.0f;                        // leader keeps final exp(u)

    int itc0 = sit[0][g], itc1 = sit[1][g];
    const uint4* ep0 = (const uint4*)(g_pk[0] + (size_t)myrow * RSTRIDE) + gl;
    const uint4* ep1 = (const uint4*)(g_pk[1] + (size_t)myrow * RSTRIDE) + gl;

    CLUSTER_SYNC();   // build + buf0 init visible cluster-wide

    // ===== 100 Sinkhorn half-iterations =====
    int p = 0;
    #pragma unroll 1
    for (int half = 0; half < 100; ++half) {
        int m = half & 1;     // 0: u update (K); 1: v update (K^T)
        const float* src = p ? buf1 : buf0;
        unsigned dst = buf_base + ((unsigned)(p ^ 1) << 13) + dst_off;  // other buf

        int iters = m ? itc1 : itc0;
        const uint4* ep = m ? ep1 : ep0;

        float acc = 0.0f;
        #pragma unroll 2
        for (int i = 0; i < iters; ++i) {
            uint4 e = ep[(size_t)i * 4];
            acc += __uint_as_float(e.x & 0xFFFFF800u) * src[e.x & 0x7FFu]
                 + __uint_as_float(e.y & 0xFFFFF800u) * src[e.y & 0x7FFu]
                 + __uint_as_float(e.z & 0xFFFFF800u) * src[e.z & 0x7FFu]
                 + __uint_as_float(e.w & 0xFFFFF800u) * src[e.w & 0x7FFu];
        }
        acc += __shfl_xor_sync(0xffffffffu, acc, 2);
        acc += __shfl_xor_sync(0xffffffffu, acc, 1);

        if (gl == 0) {
            float ev = __expf(logm - __logf(acc + 1e-8f));
            if (m == 0) myeu = ev;            // last overwrite (half 98) = final u
            #pragma unroll
            for (unsigned c = 0; c < CL; ++c)
                st_cluster(mapa_sm(dst, c), ev);
        }
        CLUSTER_SYNC();                       // scatter visible everywhere
        p ^= 1;
    }

    // ===== epilogue: emd_b = -(1/100) sum_ij k ln(k) e^{u_i} e^{v_j} =====
    // final exp(v) sits in buf[p] (input of the would-be next half)
    {
        const float* sev = p ? buf1 : buf0;
        float racc = 0.0f;
        #pragma unroll 2
        for (int i = 0; i < itc0; ++i) {
            uint4 e = ep0[(size_t)i * 4];
            unsigned b;
            b = e.x & 0xFFFFF800u;
            if (b) { float k = __uint_as_float(b); racc += k * __logf(k) * sev[e.x & 0x7FFu]; }
            b = e.y & 0xFFFFF800u;
            if (b) { float k = __uint_as_float(b); racc += k * __logf(k) * sev[e.y & 0x7FFu]; }
            b = e.z & 0xFFFFF800u;
            if (b) { float k = __uint_as_float(b); racc += k * __logf(k) * sev[e.z & 0x7FFu]; }
            b = e.w & 0xFFFFF800u;
            if (b) { float k = __uint_as_float(b); racc += k * __logf(k) * sev[e.w & 0x7FFu]; }
        }
        racc += __shfl_xor_sync(0xffffffffu, racc, 2);
        racc += __shfl_xor_sync(0xffffffffu, racc, 1);

        float acc = (gl == 0) ? racc * myeu : 0.0f;       // leaders carry row sums
        #pragma unroll
        for (int o = 16; o; o >>= 1) acc += __shfl_down_sync(0xffffffffu, acc, o);
        if (lane == 0) red[warp] = acc;
        __syncthreads();
        if (warp == 0) {
            float s = red[lane];
            #pragma unroll
            for (int o = 16; o; o >>= 1) s += __shfl_down_sync(0xffffffffu, s, o);
            if (lane == 0) {
                // deposit this CTA's partial into rank 0's cred[crank]
                unsigned a = mapa_sm(smem_u32(cred) + crank * 4, 0u);
                st_cluster(a, s);
            }
        }
    }
    CLUSTER_SYNC();

    if (crank == 0 && t == 0) {
        float s = 0.0f;
        #pragma unroll
        for (int k = 0; k < CL; ++k) s += cred[k];
        out[batch] = -s * 0.01f;              // cost = -ln(K)/100
    }
    CLUSTER_SYNC();   // no CTA exits while peers may still target its smem
}

// ---------------------------------------------------------------------------
extern "C" void kernel_launch(void* const* d_in, const int* in_sizes, int n_in,
                              void* d_out, int out_size) {
    (void)in_sizes; (void)n_in; (void)out_size;
    const float* x1 = (const float*)d_in[0];
    const float* x2 = (const float*)d_in[1];
    float* out = (float*)d_out;

    const float logm = logf(1.0f / 2048.0f + 1e-8f);
    fused_sinkhorn<<<BB * CL, TPB>>>(x1, x2, out, logm);
}

// round 8
// speedup vs baseline: 1.2127x; 1.2127x over previous
#include <cuda_runtime.h>
#include <math.h>

// Sinkhorn approximate EMD: B=8, N=2048, 3D points, 50 iterations.
// R8: single fused persistent kernel, 128 CTAs (16/batch), ONE gpu-scope
// barrier per FULL iteration. Each CTA owns 128 rows of K (packed ELL,
// L1-resident) plus a CTA-local CSC of the same rows (built once,
// deterministically via column bitmap + popc ranks). Per iteration:
//   sev_j = M/(gv_j+eps)  (multiplicative Sinkhorn — no log/exp),
//   u-gather over own rows -> expu (smem only),
//   CSC column-gather of partial colsums -> atomicAdd into gv[it],
//   barrier. K^T never materialized. Epilogue: -(1/100) sum k*lnk*eu*ev.

#define BB 8
#define NN 2048
#define NROWS (BB * NN)          // 16384
#define RSTRIDE 512              // padded max nnz per row
#define D2CUT 0.690776f          // -ln(1e-30)/100
#define CPB 16                   // CTAs per batch
#define RPC 128                  // rows per CTA
#define TPB 1024
#define CAPC 24576               // CSC entries per CTA (avg ~13.3K)
#define NIT 50

__device__ unsigned g_pk [(size_t)NROWS * RSTRIDE];      // packed ELL K (33.5 MB)
__device__ unsigned g_csc[(size_t)BB * CPB * CAPC];      // per-CTA CSC (12.6 MB)
__device__ float    g_gv [(size_t)NIT * NROWS];          // per-iter colsums (3.3 MB)
__device__ float    g_part[BB * CPB];
__device__ unsigned g_bar[BB];   // zero at load; self-reset each call

__device__ __forceinline__ void bar_arrive(unsigned* p) {
    asm volatile("red.release.gpu.add.u32 [%0], 1;" :: "l"(p) : "memory");
}
__device__ __forceinline__ unsigned bar_peek(unsigned* p) {
    unsigned v;
    asm volatile("ld.acquire.gpu.u32 %0, [%1];" : "=r"(v) : "l"(p) : "memory");
    return v;
}

// ---------------------------------------------------------------------------
__global__ __launch_bounds__(TPB, 1)
void fused_sinkhorn(const float* __restrict__ x1, const float* __restrict__ x2,
                    float* __restrict__ out, float M) {
    __shared__ __align__(16) char pool[57344];       // 56 KB
    unsigned* bitmap = (unsigned*)pool;              // [8192]  32 KB (build only)
    float*    spts   = (float*)(pool + 32768);       // [6144]  24 KB (build only)
    float*    sev    = (float*)pool;                 // [2048]  (main loop, aliases bitmap)
    __shared__ unsigned short cstart[2049];          // CSC column starts
    __shared__ float expu[RPC];
    __shared__ float red[32];
    __shared__ unsigned wsum[32];
    __shared__ unsigned char sit[RPC];               // per-row 32-entry iter counts

    int cta = blockIdx.x, batch = cta >> 4, crank = cta & (CPB - 1);
    int t = threadIdx.x, warp = t >> 5, lane = t & 31;
    int rowbase = batch * NN + crank * RPC;
    unsigned* barp = &g_bar[batch];
    unsigned target = 0;
    const float eps = 1e-8f;

    // ---- zero this CTA's slices of all gv buffers ----
    for (int i = t; i < NIT * 128; i += TPB) {
        int it = i >> 7, j = i & 127;
        __stcg(&g_gv[(size_t)it * NROWS + batch * NN + crank * 128 + j], 0.0f);
    }

    // ---- build: ELL rows of K + column bitmap ----
    for (int i = t; i < 8192; i += TPB) bitmap[i] = 0u;
    {
        const float* cp = x2 + (size_t)batch * NN * 3;
        for (int i = t; i < NN * 3; i += TPB) spts[i] = cp[i];
    }
    __syncthreads();

    #pragma unroll 1
    for (int rr = 0; rr < 4; ++rr) {                 // 4 rows per warp
        int r = warp * 4 + rr;
        int row = rowbase + r;
        const float* ap = x1 + (size_t)row * 3;
        float ax = ap[0], ay = ap[1], az = ap[2];
        unsigned* krow = g_pk + (size_t)row * RSTRIDE;

        unsigned base = 0;
        for (int c0 = 0; c0 < NN; c0 += 32) {
            int c = c0 + lane;
            float dx = ax - spts[3 * c];
            float dy = ay - spts[3 * c + 1];
            float dz = az - spts[3 * c + 2];
            float d2 = fmaf(dx, dx, fmaf(dy, dy, dz * dz));
            bool p = d2 < D2CUT;
            unsigned mk = __ballot_sync(0xffffffffu, p);
            if (p) {
                unsigned idx = base + __popc(mk & ((1u << lane) - 1u));
                if (idx < RSTRIDE) {
                    // round-to-nearest, 11-bit column in mantissa LSBs
                    krow[idx] = ((__float_as_uint(__expf(-100.0f * d2)) + 0x400u)
                                 & 0xFFFFF800u) | (unsigned)c;
                    atomicOr(&bitmap[c * 4 + (r >> 5)], 1u << (r & 31));
                }
            }
            base += __popc(mk);
        }
        unsigned nnz = (base < RSTRIDE) ? base : RSTRIDE;
        unsigned pad = (nnz + 31u) & ~31u;
        for (unsigned idx = nnz + lane; idx < pad; idx += 32) krow[idx] = 0u;
        if (lane == 0) sit[r] = (unsigned char)(pad >> 5);
    }
    __syncthreads();

    // ---- column counts + exclusive scan (thread t owns cols 2t, 2t+1) ----
    {
        int c0 = 2 * t, c1 = 2 * t + 1;
        unsigned n0 = __popc(bitmap[c0 * 4]) + __popc(bitmap[c0 * 4 + 1])
                    + __popc(bitmap[c0 * 4 + 2]) + __popc(bitmap[c0 * 4 + 3]);
        unsigned n1 = __popc(bitmap[c1 * 4]) + __popc(bitmap[c1 * 4 + 1])
                    + __popc(bitmap[c1 * 4 + 2]) + __popc(bitmap[c1 * 4 + 3]);
        unsigned tot = n0 + n1, s = tot;
        #pragma unroll
        for (int o = 1; o < 32; o <<= 1) {
            unsigned x = __shfl_up_sync(0xffffffffu, s, o);
            if (lane >= o) s += x;
        }
        if (lane == 31) wsum[warp] = s;
        __syncthreads();
        if (warp == 0) {
            unsigned w = wsum[lane];
            #pragma unroll
            for (int o = 1; o < 32; o <<= 1) {
                unsigned x = __shfl_up_sync(0xffffffffu, w, o);
                if (lane >= o) w += x;
            }
            wsum[lane] = w;
        }
        __syncthreads();
        unsigned base = (warp ? wsum[warp - 1] : 0u) + s - tot;
        cstart[c0] = (unsigned short)base;
        cstart[c1] = (unsigned short)(base + n0);
        if (t == TPB - 1) cstart[2048] = (unsigned short)(base + tot);
    }
    __syncthreads();

    // ---- CSC fill (deterministic: rank via bitmap popcount) ----
    {
        unsigned* cbase = g_csc + (size_t)cta * CAPC;
        #pragma unroll 1
        for (int rr = 0; rr < 4; ++rr) {
            int r = warp * 4 + rr;
            const unsigned* krow = g_pk + (size_t)(rowbase + r) * RSTRIDE;
            int n = (int)sit[r] * 32;
            for (int k = lane; k < n; k += 32) {
                unsigned u = krow[k];
                if (u) {
                    unsigned c = u & 0x7FFu;
                    unsigned w = (unsigned)r >> 5;
                    unsigned rank = 0;
                    for (unsigned ww = 0; ww < w; ++ww)
                        rank += __popc(bitmap[c * 4 + ww]);
                    rank += __popc(bitmap[c * 4 + w] & ((1u << (r & 31)) - 1u));
                    unsigned pos = cstart[c] + rank;
                    if (pos < CAPC)
                        cbase[pos] = (u & 0xFFFFF800u) | (unsigned)r;  // 7-bit row
                }
            }
        }
    }
    __threadfence();
    __syncthreads();

    // barrier round 1: gv zeroing (and build) complete batch-wide
    target += CPB;
    if (t == 0) { bar_arrive(barp); while (bar_peek(barp) < target) { } }
    __syncthreads();

    // ---- main loop: 50 full iterations, ONE barrier each ----
    int g = t >> 3, gl = t & 7;                  // 128 groups x 8 lanes
    int iters = sit[g];
    const uint4* ep = (const uint4*)(g_pk + (size_t)(rowbase + g) * RSTRIDE) + gl;
    const unsigned* cbase = g_csc + (size_t)cta * CAPC;

    #pragma unroll 1
    for (int it = 0; it < NIT; ++it) {
        // stage sev_j = exp(v_j) = M / (colsum_j + eps); it=0: exp(v0)=1
        if (it == 0) {
            ((float2*)sev)[t] = make_float2(1.0f, 1.0f);
        } else {
            const float2* gs = (const float2*)(g_gv + (size_t)(it - 1) * NROWS + batch * NN);
            float2 gx = __ldcg(gs + t);
            float2 e;
            e.x = __fdividef(M, gx.x + eps);
            e.y = __fdividef(M, gx.y + eps);
            ((float2*)sev)[t] = e;
        }
        __syncthreads();

        // u-gather: rowsum over own row; expu = M/(rowsum+eps)
        float acc = 0.0f;
        #pragma unroll 2
        for (int i = 0; i < iters; ++i) {
            uint4 e = ep[(size_t)i * 8];
            acc += __uint_as_float(e.x & 0xFFFFF800u) * sev[e.x & 0x7FFu]
                 + __uint_as_float(e.y & 0xFFFFF800u) * sev[e.y & 0x7FFu]
                 + __uint_as_float(e.z & 0xFFFFF800u) * sev[e.z & 0x7FFu]
                 + __uint_as_float(e.w & 0xFFFFF800u) * sev[e.w & 0x7FFu];
        }
        acc += __shfl_xor_sync(0xffffffffu, acc, 4);
        acc += __shfl_xor_sync(0xffffffffu, acc, 2);
        acc += __shfl_xor_sync(0xffffffffu, acc, 1);
        if (gl == 0) expu[g] = __fdividef(M, acc + eps);
        __syncthreads();

        // partial colsums via CSC; add into gv[it]
        float* gvd = g_gv + (size_t)it * NROWS + batch * NN;
        for (int j = t; j < NN; j += TPB) {
            unsigned k0 = cstart[j], k1 = cstart[j + 1];
            float s = 0.0f;
            for (unsigned k = k0; k < k1; ++k) {
                unsigned e = cbase[k];
                s += __uint_as_float(e & 0xFFFFF800u) * expu[e & 0x7Fu];
            }
            atomicAdd(gvd + j, s);
        }
        __threadfence();
        __syncthreads();

        target += CPB;
        if (t == 0) { bar_arrive(barp); while (bar_peek(barp) < target) { } }
        __syncthreads();
    }

    // ---- epilogue: emd_b = -(1/100) sum_ij k ln(k) e^{u_i} e^{v_j} ----
    {
        const float2* gs = (const float2*)(g_gv + (size_t)(NIT - 1) * NROWS + batch * NN);
        float2 gx = __ldcg(gs + t);
        float2 e;
        e.x = __fdividef(M, gx.x + eps);
        e.y = __fdividef(M, gx.y + eps);
        ((float2*)sev)[t] = e;                       // final exp(v)
    }
    __syncthreads();

    float racc = 0.0f;
    #pragma unroll 2
    for (int i = 0; i < iters; ++i) {
        uint4 e = ep[(size_t)i * 8];
        unsigned b;
        b = e.x & 0xFFFFF800u;
        if (b) { float k = __uint_as_float(b); racc += k * __logf(k) * sev[e.x & 0x7FFu]; }
        b = e.y & 0xFFFFF800u;
        if (b) { float k = __uint_as_float(b); racc += k * __logf(k) * sev[e.y & 0x7FFu]; }
        b = e.z & 0xFFFFF800u;
        if (b) { float k = __uint_as_float(b); racc += k * __logf(k) * sev[e.z & 0x7FFu]; }
        b = e.w & 0xFFFFF800u;
        if (b) { float k = __uint_as_float(b); racc += k * __logf(k) * sev[e.w & 0x7FFu]; }
    }
    racc += __shfl_xor_sync(0xffffffffu, racc, 4);
    racc += __shfl_xor_sync(0xffffffffu, racc, 2);
    racc += __shfl_xor_sync(0xffffffffu, racc, 1);

    float acc = (gl == 0) ? racc * expu[g] : 0.0f;   // leaders carry row sums
    #pragma unroll
    for (int o = 16; o; o >>= 1) acc += __shfl_down_sync(0xffffffffu, acc, o);
    if (lane == 0) red[warp] = acc;
    __syncthreads();
    if (warp == 0) {
        float s = red[lane];
        #pragma unroll
        for (int o = 16; o; o >>= 1) s += __shfl_down_sync(0xffffffffu, s, o);
        if (lane == 0) __stcg(&g_part[cta], s);      // t==0 stores
    }
    __syncthreads();

    target += CPB;
    if (t == 0) {
        bar_arrive(barp);                            // release covers t0's g_part store
        if (crank == 0) {
            while (bar_peek(barp) < target) { }
            float s = 0.0f;
            #pragma unroll
            for (int k = 0; k < CPB; ++k) s += __ldcg(&g_part[batch * CPB + k]);
            out[batch] = -s * 0.01f;                 // cost = -ln(K)/100
            *barp = 0u;                              // reset for next replay
        }
    }
}

// ---------------------------------------------------------------------------
extern "C" void kernel_launch(void* const* d_in, const int* in_sizes, int n_in,
                              void* d_out, int out_size) {
    (void)in_sizes; (void)n_in; (void)out_size;
    const float* x1 = (const float*)d_in[0];
    const float* x2 = (const float*)d_in[1];
    float* out = (float*)d_out;

    const float M = 1.0f / 2048.0f + 1e-8f;          // exp(log(mu + eps_log))
    fused_sinkhorn<<<BB * CPB, TPB>>>(x1, x2, out, M);
}

// round 9
// speedup vs baseline: 1.2579x; 1.0373x over previous
#include <cuda_runtime.h>
#include <math.h>

// Sinkhorn approximate EMD: B=8, N=2048, 3D points, 50 iterations.
// R9: fused persistent kernel (128 CTAs, 16/batch, 512 thr). Packed-ELL
// K and K^T with cutoff K >= 1e-14 (~1.3% density, 3x fewer entries than
// R6; dropped mass ~1e-6 abs, far under tolerance). 4-lane groups, 16
// entries per group-iter. Multiplicative updates (one fast divide, no
// log/exp in loop). Poll-all gpu-scope barrier, 2 per iteration.

#define BB 8
#define NN 2048
#define NROWS (BB * NN)          // 16384
#define RSTRIDE 256              // padded max nnz per row (avg ~27, center ~100)
#define D2CUT 0.322362f          // ln(1e14)/100
#define CPB 16                   // CTAs per batch
#define RPC 128                  // rows per CTA
#define TPB 512                  // 128 groups x 4 lanes

__device__ unsigned g_pk[2][(size_t)NROWS * RSTRIDE];   // packed K / K^T (33.5 MB)
__device__ float    g_expu[NROWS], g_expv[NROWS];
__device__ float    g_part[BB * CPB];
__device__ unsigned g_bar[BB];   // zero at load; self-reset each call

__device__ __forceinline__ void bar_arrive(unsigned* p) {
    asm volatile("red.release.gpu.add.u32 [%0], 1;" :: "l"(p) : "memory");
}
__device__ __forceinline__ unsigned bar_peek(unsigned* p) {
    unsigned v;
    asm volatile("ld.acquire.gpu.u32 %0, [%1];" : "=r"(v) : "l"(p) : "memory");
    return v;
}

// ---------------------------------------------------------------------------
__global__ __launch_bounds__(TPB, 2)
void fused_sinkhorn(const float* __restrict__ x1, const float* __restrict__ x2,
                    float* __restrict__ out, float M) {
    __shared__ float sxbuf[NN * 3];          // build staging; first 2048 reused as sev
    __shared__ unsigned char sit[2][RPC];    // per-row 16-entry iteration counts
    __shared__ float red[16];
    float* sev = sxbuf;

    int cta = blockIdx.x, batch = cta >> 4, crank = cta & (CPB - 1);
    int t = threadIdx.x, warp = t >> 5, lane = t & 31;
    int rowbase = batch * NN + crank * RPC;
    unsigned* barp = &g_bar[batch];
    unsigned target = 0;
    const float eps = 1e-8f;

    // ===== inline build: CTA-private packed-ELL rows of K and K^T =====
    #pragma unroll 1
    for (int m = 0; m < 2; ++m) {
        const float* rowpts = m ? x2 : x1;
        const float* colpts = m ? x1 : x2;
        const float* cp = colpts + (size_t)batch * NN * 3;
        for (int i = t; i < NN * 3; i += TPB) sxbuf[i] = cp[i];
        __syncthreads();

        #pragma unroll 1
        for (int rr = 0; rr < 8; ++rr) {             // 8 rows per warp
            int r   = warp * 8 + rr;
            int row = rowbase + r;
            const float* ap = rowpts + (size_t)row * 3;
            float ax = ap[0], ay = ap[1], az = ap[2];
            unsigned* krow = g_pk[m] + (size_t)row * RSTRIDE;

            unsigned base = 0;
            for (int c0 = 0; c0 < NN; c0 += 32) {
                int c = c0 + lane;
                float dx = ax - sxbuf[3 * c];
                float dy = ay - sxbuf[3 * c + 1];
                float dz = az - sxbuf[3 * c + 2];
                float d2 = fmaf(dx, dx, fmaf(dy, dy, dz * dz));
                bool p = d2 < D2CUT;
                unsigned mk = __ballot_sync(0xffffffffu, p);
                if (p) {
                    unsigned idx = base + __popc(mk & ((1u << lane) - 1u));
                    if (idx < RSTRIDE)   // RN-rounded 21-bit val | 11-bit col
                        krow[idx] = ((__float_as_uint(__expf(-100.0f * d2)) + 0x400u)
                                     & 0xFFFFF800u) | (unsigned)c;
                }
                base += __popc(mk);
            }
            unsigned nnz = (base < RSTRIDE) ? base : RSTRIDE;
            unsigned pad = (nnz + 15u) & ~15u;       // 16-entry group iterations
            for (unsigned idx = nnz + lane; idx < pad; idx += 32) krow[idx] = 0u;
            if (lane == 0) sit[m][r] = (unsigned char)(pad >> 4);
        }
        __syncthreads();
    }

    // ===== 100 Sinkhorn half-iterations =====
    int g = t >> 2, gl = t & 3;                      // 128 groups x 4 lanes
    int myrow = rowbase + g;
    int itc0 = sit[0][g], itc1 = sit[1][g];
    const uint4* ep0 = (const uint4*)(g_pk[0] + (size_t)myrow * RSTRIDE) + gl;
    const uint4* ep1 = (const uint4*)(g_pk[1] + (size_t)myrow * RSTRIDE) + gl;

    #pragma unroll 1
    for (int half = 0; half < 100; ++half) {
        int m = half & 1;   // 0: u update (K, reads expv); 1: v update (K^T, reads expu)

        // stage source exp-vector (all 512 threads, 4 floats each)
        if (half == 0) {
            ((float4*)sev)[t] = make_float4(1.f, 1.f, 1.f, 1.f);   // exp(v0)=1
        } else {
            ((float4*)sev)[t] =
                __ldcg((const float4*)((m ? g_expu : g_expv) + batch * NN) + t);
        }
        __syncthreads();

        int iters = m ? itc1 : itc0;
        const uint4* ep = m ? ep1 : ep0;
        float acc = 0.0f;
        #pragma unroll 2
        for (int i = 0; i < iters; ++i) {
            uint4 e = ep[(size_t)i * 4];
            acc += __uint_as_float(e.x & 0xFFFFF800u) * sev[e.x & 0x7FFu]
                 + __uint_as_float(e.y & 0xFFFFF800u) * sev[e.y & 0x7FFu]
                 + __uint_as_float(e.z & 0xFFFFF800u) * sev[e.z & 0x7FFu]
                 + __uint_as_float(e.w & 0xFFFFF800u) * sev[e.w & 0x7FFu];
        }
        acc += __shfl_xor_sync(0xffffffffu, acc, 2);
        acc += __shfl_xor_sync(0xffffffffu, acc, 1);

        if (gl == 0) {   // multiplicative update: exp(new) = M / (sum + eps)
            float ev = __fdividef(M, acc + eps);
            __stcg((m ? g_expv : g_expu) + myrow, ev);
        }
        __syncthreads();                 // all stcg issued before arrive

        target += CPB;
        if (t == 0) bar_arrive(barp);
        while (bar_peek(barp) < target) { }          // poll-all, broadcast load
    }

    // ===== epilogue: emd_b = -(1/100) sum_ij k ln(k) e^{u_i} e^{v_j} =====
    ((float4*)sev)[t] = __ldcg((const float4*)(g_expv + batch * NN) + t);
    __syncthreads();

    float racc = 0.0f;
    #pragma unroll 2
    for (int i = 0; i < itc0; ++i) {
        uint4 e = ep0[(size_t)i * 4];
        unsigned b;
        b = e.x & 0xFFFFF800u;
        if (b) { float k = __uint_as_float(b); racc += k * __logf(k) * sev[e.x & 0x7FFu]; }
        b = e.y & 0xFFFFF800u;
        if (b) { float k = __uint_as_float(b); racc += k * __logf(k) * sev[e.y & 0x7FFu]; }
        b = e.z & 0xFFFFF800u;
        if (b) { float k = __uint_as_float(b); racc += k * __logf(k) * sev[e.z & 0x7FFu]; }
        b = e.w & 0xFFFFF800u;
        if (b) { float k = __uint_as_float(b); racc += k * __logf(k) * sev[e.w & 0x7FFu]; }
    }
    racc += __shfl_xor_sync(0xffffffffu, racc, 2);
    racc += __shfl_xor_sync(0xffffffffu, racc, 1);

    float eu = __ldcg(g_expu + myrow);
    float acc = (gl == 0) ? racc * eu : 0.0f;        // leaders carry row sums
    #pragma unroll
    for (int o = 16; o; o >>= 1) acc += __shfl_down_sync(0xffffffffu, acc, o);
    if (lane == 0) red[warp] = acc;
    __syncthreads();
    if (warp == 0) {
        float s = (lane < 16) ? red[lane] : 0.0f;
        #pragma unroll
        for (int o = 8; o; o >>= 1) s += __shfl_down_sync(0xffffffffu, s, o);
        if (lane == 0) __stcg(&g_part[cta], s);
    }
    __syncthreads();

    target += CPB;
    if (t == 0) {
        bar_arrive(barp);                // release covers the g_part store
        if (crank == 0) {                // only rank 0 waits; others exit
            while (bar_peek(barp) < target) { }
            float s = 0.0f;
            #pragma unroll
            for (int k = 0; k < CPB; ++k) s += __ldcg(&g_part[batch * CPB + k]);
            out[batch] = -s * 0.01f;     // cost = -ln(K)/100
            *barp = 0u;                  // reset for next graph replay
        }
    }
}

// ---------------------------------------------------------------------------
extern "C" void kernel_launch(void* const* d_in, const int* in_sizes, int n_in,
                              void* d_out, int out_size) {
    (void)in_sizes; (void)n_in; (void)out_size;
    const float* x1 = (const float*)d_in[0];
    const float* x2 = (const float*)d_in[1];
    float* out = (float*)d_out;

    const float M = 1.0f / 2048.0f + 1e-8f;   // exp(log(1/N + eps_log))
    fused_sinkhorn<<<BB * CPB, TPB>>>(x1, x2, out, M);
}